// round 14
// baseline (speedup 1.0000x reference)
#include <cuda_runtime.h>

#define DD 64
#define H_ 256
#define W_ 512
#define HW_ (H_ * W_)
#define B_ 8
#define NPIX (B_ * HW_)
#define VEC 4
#define TPB 128
#define NTILES (NPIX / VEC / TPB)      // 2048 tiles of TPB*VEC pixels
#define NBLOCKS 1184                    // 148 SMs * 8 blocks: exactly one full wave

__device__ double g_part[NBLOCKS];
__device__ unsigned int g_pcnt[NBLOCKS];
__device__ unsigned int g_ticket;      // zero-init at load; last block resets each launch

__global__ __launch_bounds__(TPB, 8) void sce_main(const float* __restrict__ sim,
                                                   const float* __restrict__ gt,
                                                   float* __restrict__ out) {
    int tid = threadIdx.x;

    const float E1  = 2.718281828459045f;    // e
    const float IE1 = 0.3678794411714423f;   // 1/e
    const float C1  = 0.15651764274966565f;  // 1/(e^2-1)
    const float C2  = 1.1565176427496657f;   // 1/(1-e^-2)

    double lsum = 0.0;
    unsigned int lcnt = 0u;

#pragma unroll 1
    for (int tile = blockIdx.x; tile < NTILES; tile += NBLOCKS) {
        int t = tile * TPB + tid;
        long long base = (long long)t * VEC;
        int b = (int)(base / HW_);
        int hw = (int)(base - (long long)b * HW_);

        float4 g4 = *reinterpret_cast<const float4*>(gt + base);
        float gts[VEC] = {g4.x, g4.y, g4.z, g4.w};

        // u_d = e^{(2d-gt)/2}, v_d = e^{(gt-2d)/2}; p_d = exp(-|gt-2d|) = min(u,v)^2
        float u[VEC], v[VEC], esum[VEC], pts[VEC];
#pragma unroll
        for (int j = 0; j < VEC; ++j) {
            float hg = 0.5f * gts[j];
            u[j] = __expf(-hg);
            v[j] = __expf(hg);
            esum[j] = 0.f; pts[j] = 0.f;
        }

        const float* sbase = sim + (long long)b * DD * HW_ + hw;

        auto body = [&](float4 s4) {
            float sv[VEC] = {s4.x, s4.y, s4.z, s4.w};
#pragma unroll
            for (int j = 0; j < VEC; ++j) {
                float s = sv[j];
                esum[j] += __expf(s);
                float mm = fminf(u[j], v[j]);
                pts[j] = fmaf(mm * mm, s, pts[j]);
                u[j] *= E1;
                v[j] *= IE1;
            }
        };

        // A/B ping-pong double buffer, batch = 4 planes (R9 structure).
        float4 bufA[4], bufB[4];
#pragma unroll
        for (int k = 0; k < 4; ++k)
            bufA[k] = __ldcs(reinterpret_cast<const float4*>(sbase + (long long)k * HW_));

#pragma unroll 1
        for (int db = 0; db < DD - 8; db += 8) {
#pragma unroll
            for (int k = 0; k < 4; ++k)
                bufB[k] = __ldcs(reinterpret_cast<const float4*>(sbase + (long long)(db + 4 + k) * HW_));
#pragma unroll
            for (int k = 0; k < 4; ++k) body(bufA[k]);
#pragma unroll
            for (int k = 0; k < 4; ++k)
                bufA[k] = __ldcs(reinterpret_cast<const float4*>(sbase + (long long)(db + 8 + k) * HW_));
#pragma unroll
            for (int k = 0; k < 4; ++k) body(bufB[k]);
        }
#pragma unroll
        for (int k = 0; k < 4; ++k)
            bufB[k] = __ldcs(reinterpret_cast<const float4*>(sbase + (long long)(DD - 4 + k) * HW_));
#pragma unroll
        for (int k = 0; k < 4; ++k) body(bufA[k]);
#pragma unroll
        for (int k = 0; k < 4; ++k) body(bufB[k]);

#pragma unroll
        for (int j = 0; j < VEC; ++j) {
            if (isfinite(gts[j])) {
                // ptn closed form: t' = gt-2*floor(gt/2); two geometric series
                float gtv = gts[j];
                float m0 = floorf(gtv * 0.5f);
                float tt = fmaf(-2.0f, m0, gtv);
                float et2 = __expf(tt - 2.0f);
                float e2t = 1.0f / et2;
                float eng = __expf(-gtv);
                float wsq = __expf(gtv - 128.0f);
                float ptn = (e2t - eng) * C1 + (et2 - wsq) * C2;
                float ent = __logf(esum[j]) - pts[j] / ptn;
                lsum += (double)ent;
                lcnt++;
            }
        }
    }

    const unsigned mask = 0xffffffffu;
#pragma unroll
    for (int o = 16; o > 0; o >>= 1) {
        lsum += __shfl_down_sync(mask, lsum, o);
        lcnt += __shfl_down_sync(mask, lcnt, o);
    }

    __shared__ double ssum[TPB / 32];
    __shared__ unsigned int scnt[TPB / 32];
    __shared__ int s_last;
    int lane = tid & 31;
    int warp = tid >> 5;
    if (lane == 0) { ssum[warp] = lsum; scnt[warp] = lcnt; }
    __syncthreads();

    if (warp == 0) {
        lsum = (lane < TPB / 32) ? ssum[lane] : 0.0;
        lcnt = (lane < TPB / 32) ? scnt[lane] : 0u;
#pragma unroll
        for (int o = 2; o > 0; o >>= 1) {
            lsum += __shfl_down_sync(mask, lsum, o);
            lcnt += __shfl_down_sync(mask, lcnt, o);
        }
        if (lane == 0) {
            g_part[blockIdx.x] = lsum;
            g_pcnt[blockIdx.x] = lcnt;
            __threadfence();
            unsigned int ticket = atomicAdd(&g_ticket, 1u);
            s_last = (ticket == NBLOCKS - 1);
        }
    }
    __syncthreads();

    // Fused finalize: last block reduces all partials.
    if (s_last) {
        double s = 0.0;
        unsigned int c = 0u;
#pragma unroll 4
        for (int i = tid; i < NBLOCKS; i += TPB) {
            s += __ldcg(&g_part[i]);
            c += __ldcg(&g_pcnt[i]);
        }
#pragma unroll
        for (int o = 16; o > 0; o >>= 1) {
            s += __shfl_down_sync(mask, s, o);
            c += __shfl_down_sync(mask, c, o);
        }
        __syncthreads();
        if (lane == 0) { ssum[warp] = s; scnt[warp] = c; }
        __syncthreads();
        if (warp == 0) {
            s = (lane < TPB / 32) ? ssum[lane] : 0.0;
            c = (lane < TPB / 32) ? scnt[lane] : 0u;
#pragma unroll
            for (int o = 2; o > 0; o >>= 1) {
                s += __shfl_down_sync(mask, s, o);
                c += __shfl_down_sync(mask, c, o);
            }
            if (lane == 0) {
                out[0] = (float)(s / (double)c);
                g_ticket = 0u;
                __threadfence();
            }
        }
    }
}

extern "C" void kernel_launch(void* const* d_in, const int* in_sizes, int n_in,
                              void* d_out, int out_size) {
    const float* sim = (const float*)d_in[0];
    const float* gt  = (const float*)d_in[1];
    float* out = (float*)d_out;

    sce_main<<<NBLOCKS, TPB>>>(sim, gt, out);
}

// round 15
// speedup vs baseline: 1.0484x; 1.0484x over previous
#include <cuda_runtime.h>

#define DD 64
#define H_ 256
#define W_ 512
#define HW_ (H_ * W_)
#define B_ 8
#define NPIX (B_ * HW_)
#define VEC 4
#define TPB 128
#define NTILES (NPIX / VEC / TPB)      // 2048 tiles
#define NBLOCKS (NTILES / 2)           // 1024 CTAs, 2 tiles each: one uniform wave
#define TILES_PER_CTA 2

__device__ double g_part[NBLOCKS];
__device__ unsigned int g_pcnt[NBLOCKS];
__device__ unsigned int g_ticket;      // zero-init at load; last block resets each launch

__global__ __launch_bounds__(TPB, 8) void sce_main(const float* __restrict__ sim,
                                                   const float* __restrict__ gt,
                                                   float* __restrict__ out) {
    int tid = threadIdx.x;

    const float E1  = 2.718281828459045f;    // e
    const float IE1 = 0.3678794411714423f;   // 1/e
    const float C1  = 0.15651764274966565f;  // 1/(e^2-1)
    const float C2  = 1.1565176427496657f;   // 1/(1-e^-2)

    double lsum = 0.0;
    unsigned int lcnt = 0u;

    // Per-tile base pointers (tile i of this CTA = blockIdx.x + i*NBLOCKS)
    const float* sb[TILES_PER_CTA];
    long long gbase[TILES_PER_CTA];
#pragma unroll
    for (int i = 0; i < TILES_PER_CTA; ++i) {
        int t = (blockIdx.x + i * NBLOCKS) * TPB + tid;
        long long base = (long long)t * VEC;
        int b = (int)(base / HW_);
        int hw = (int)(base - (long long)b * HW_);
        sb[i] = sim + (long long)b * DD * HW_ + hw;
        gbase[i] = base;
    }

    // Pipeline buffers persist across tiles (cross-tile prefetch).
    float4 bufA[4], bufB[4];
#pragma unroll
    for (int k = 0; k < 4; ++k)
        bufA[k] = __ldcs(reinterpret_cast<const float4*>(sb[0] + (long long)k * HW_));

#pragma unroll
    for (int tile = 0; tile < TILES_PER_CTA; ++tile) {
        const float* sbase = sb[tile];

        float4 g4 = *reinterpret_cast<const float4*>(gt + gbase[tile]);
        float gts[VEC] = {g4.x, g4.y, g4.z, g4.w};

        // u_d = e^{(2d-gt)/2}, v_d = e^{(gt-2d)/2}; p_d = exp(-|gt-2d|) = min(u,v)^2
        float u[VEC], v[VEC], esum[VEC], pts[VEC];
#pragma unroll
        for (int j = 0; j < VEC; ++j) {
            float hg = 0.5f * gts[j];
            u[j] = __expf(-hg);
            v[j] = __expf(hg);
            esum[j] = 0.f; pts[j] = 0.f;
        }

        auto body = [&](float4 s4) {
            float sv[VEC] = {s4.x, s4.y, s4.z, s4.w};
#pragma unroll
            for (int j = 0; j < VEC; ++j) {
                float s = sv[j];
                esum[j] += __expf(s);
                float mm = fminf(u[j], v[j]);
                pts[j] = fmaf(mm * mm, s, pts[j]);
                u[j] *= E1;
                v[j] *= IE1;
            }
        };

        // A/B ping-pong double buffer, batch = 4 planes (R9/R13 proven structure).
#pragma unroll 1
        for (int db = 0; db < DD - 8; db += 8) {
#pragma unroll
            for (int k = 0; k < 4; ++k)
                bufB[k] = __ldcs(reinterpret_cast<const float4*>(sbase + (long long)(db + 4 + k) * HW_));
#pragma unroll
            for (int k = 0; k < 4; ++k) body(bufA[k]);
#pragma unroll
            for (int k = 0; k < 4; ++k)
                bufA[k] = __ldcs(reinterpret_cast<const float4*>(sbase + (long long)(db + 8 + k) * HW_));
#pragma unroll
            for (int k = 0; k < 4; ++k) body(bufB[k]);
        }
        // bufA holds planes 56..59. Load 60..63, consume A, prefetch next tile, consume B.
#pragma unroll
        for (int k = 0; k < 4; ++k)
            bufB[k] = __ldcs(reinterpret_cast<const float4*>(sbase + (long long)(DD - 4 + k) * HW_));
#pragma unroll
        for (int k = 0; k < 4; ++k) body(bufA[k]);
        if (tile + 1 < TILES_PER_CTA) {
            // Cross-tile prefetch: next tile's planes 0..3 land while bufB drains
            // and the tile epilogue below executes.
#pragma unroll
            for (int k = 0; k < 4; ++k)
                bufA[k] = __ldcs(reinterpret_cast<const float4*>(sb[tile + 1] + (long long)k * HW_));
        }
#pragma unroll
        for (int k = 0; k < 4; ++k) body(bufB[k]);

#pragma unroll
        for (int j = 0; j < VEC; ++j) {
            if (isfinite(gts[j])) {
                // ptn closed form: t' = gt-2*floor(gt/2); two geometric series
                float gtv = gts[j];
                float m0 = floorf(gtv * 0.5f);
                float tt = fmaf(-2.0f, m0, gtv);
                float et2 = __expf(tt - 2.0f);
                float e2t = 1.0f / et2;
                float eng = __expf(-gtv);
                float wsq = __expf(gtv - 128.0f);
                float ptn = (e2t - eng) * C1 + (et2 - wsq) * C2;
                float ent = __logf(esum[j]) - pts[j] / ptn;
                lsum += (double)ent;
                lcnt++;
            }
        }
    }

    const unsigned mask = 0xffffffffu;
#pragma unroll
    for (int o = 16; o > 0; o >>= 1) {
        lsum += __shfl_down_sync(mask, lsum, o);
        lcnt += __shfl_down_sync(mask, lcnt, o);
    }

    __shared__ double ssum[TPB / 32];
    __shared__ unsigned int scnt[TPB / 32];
    __shared__ int s_last;
    int lane = tid & 31;
    int warp = tid >> 5;
    if (lane == 0) { ssum[warp] = lsum; scnt[warp] = lcnt; }
    __syncthreads();

    if (warp == 0) {
        lsum = (lane < TPB / 32) ? ssum[lane] : 0.0;
        lcnt = (lane < TPB / 32) ? scnt[lane] : 0u;
#pragma unroll
        for (int o = 2; o > 0; o >>= 1) {
            lsum += __shfl_down_sync(mask, lsum, o);
            lcnt += __shfl_down_sync(mask, lcnt, o);
        }
        if (lane == 0) {
            g_part[blockIdx.x] = lsum;
            g_pcnt[blockIdx.x] = lcnt;
            __threadfence();
            unsigned int ticket = atomicAdd(&g_ticket, 1u);
            s_last = (ticket == NBLOCKS - 1);
        }
    }
    __syncthreads();

    // Fused finalize: last block reduces all partials.
    if (s_last) {
        double s = 0.0;
        unsigned int c = 0u;
#pragma unroll 4
        for (int i = tid; i < NBLOCKS; i += TPB) {
            s += __ldcg(&g_part[i]);
            c += __ldcg(&g_pcnt[i]);
        }
#pragma unroll
        for (int o = 16; o > 0; o >>= 1) {
            s += __shfl_down_sync(mask, s, o);
            c += __shfl_down_sync(mask, c, o);
        }
        __syncthreads();
        if (lane == 0) { ssum[warp] = s; scnt[warp] = c; }
        __syncthreads();
        if (warp == 0) {
            s = (lane < TPB / 32) ? ssum[lane] : 0.0;
            c = (lane < TPB / 32) ? scnt[lane] : 0u;
#pragma unroll
            for (int o = 2; o > 0; o >>= 1) {
                s += __shfl_down_sync(mask, s, o);
                c += __shfl_down_sync(mask, c, o);
            }
            if (lane == 0) {
                out[0] = (float)(s / (double)c);
                g_ticket = 0u;
                __threadfence();
            }
        }
    }
}

extern "C" void kernel_launch(void* const* d_in, const int* in_sizes, int n_in,
                              void* d_out, int out_size) {
    const float* sim = (const float*)d_in[0];
    const float* gt  = (const float*)d_in[1];
    float* out = (float*)d_out;

    sce_main<<<NBLOCKS, TPB>>>(sim, gt, out);
}